// round 4
// baseline (speedup 1.0000x reference)
#include <cuda_runtime.h>

// WideComponent: out[b] = emb_user[u[b]] + emb_item[i[b]] + emb_cat[c[b]]
//                       + cross_w[u[b]*D_CAT + c[b]]
//                       + cross_w[OFF_IC + i[b]*D_CAT + c[b]]
// D_USER=100000, D_ITEM=50000, D_CAT=1000, OFF_IC = 100,000,000. B = 16384.
//
// R3: 4 elements/thread, int4 index loads + float4 store. 4096 threads =
// 128 warps = 32 CTAs x 128. Cuts dynamic instruction count ~4x and
// shortens prologue/drain tail; 20 independent gathers in flight per thread.

static constexpr int D_CAT  = 1000;
static constexpr int OFF_IC = 100000 * D_CAT;  // 100,000,000
static constexpr int B_TOTAL = 16384;
static constexpr int VEC = 4;

__global__ void __launch_bounds__(128) wide_kernel(
    const int4*  __restrict__ user_id,    // B/4 int4
    const int4*  __restrict__ item_id,
    const int4*  __restrict__ category,
    const float* __restrict__ emb_user,
    const float* __restrict__ emb_item,
    const float* __restrict__ emb_cat,
    const float* __restrict__ cross_w,
    float4*      __restrict__ out)
{
    int t = blockIdx.x * blockDim.x + threadIdx.x;  // 0 .. 4095, exact grid

    // Three vectorized index loads (fully coalesced 16B per thread)
    int4 u4 = __ldg(&user_id[t]);
    int4 i4 = __ldg(&item_id[t]);
    int4 c4 = __ldg(&category[t]);

    const int u[VEC] = {u4.x, u4.y, u4.z, u4.w};
    const int i[VEC] = {i4.x, i4.y, i4.z, i4.w};
    const int c[VEC] = {c4.x, c4.y, c4.z, c4.w};

    // 20 independent gathers — ptxas front-batches them (high MLP).
    float wu[VEC], wi[VEC], wc[VEC], xu[VEC], xi[VEC];
#pragma unroll
    for (int k = 0; k < VEC; k++) {
        wu[k] = __ldg(&emb_user[u[k]]);
        wi[k] = __ldg(&emb_item[i[k]]);
        wc[k] = __ldg(&emb_cat[c[k]]);
        xu[k] = __ldg(&cross_w[u[k] * D_CAT + c[k]]);
        xi[k] = __ldg(&cross_w[OFF_IC + i[k] * D_CAT + c[k]]);
    }

    float4 r;
    r.x = wu[0] + wi[0] + wc[0] + xu[0] + xi[0];
    r.y = wu[1] + wi[1] + wc[1] + xu[1] + xi[1];
    r.z = wu[2] + wi[2] + wc[2] + xu[2] + xi[2];
    r.w = wu[3] + wi[3] + wc[3] + xu[3] + xi[3];
    out[t] = r;
}

extern "C" void kernel_launch(void* const* d_in, const int* in_sizes, int n_in,
                              void* d_out, int out_size)
{
    const int4*  user_id  = (const int4*) d_in[0];
    const int4*  item_id  = (const int4*) d_in[1];
    const int4*  category = (const int4*) d_in[2];
    const float* emb_user = (const float*)d_in[3];
    const float* emb_item = (const float*)d_in[4];
    const float* emb_cat  = (const float*)d_in[5];
    const float* cross_w  = (const float*)d_in[6];
    float4*      out      = (float4*)d_out;

    // B = 16384 -> 4096 threads -> 32 CTAs x 128 (exact, no bounds check)
    wide_kernel<<<(B_TOTAL / VEC) / 128, 128>>>(user_id, item_id, category,
                                                emb_user, emb_item, emb_cat,
                                                cross_w, out);
}